// round 8
// baseline (speedup 1.0000x reference)
#include <cuda_runtime.h>
#include <math.h>
#include <float.h>

#define NPTS 16384
#define HDIM 256
#define HD2  128
#define TR   32          // rows per block in emb kernel
#define TRP  36          // padded row stride (floats), 16B-aligned
#define GRID 192
#define NCELLS (GRID * GRID)      // 36864 = 1024 * 36
#define HCELL 0.5f
#define INVH  2.0f
#define LHALF 48.0f

typedef unsigned long long u64;

// ---------------- static device scratch (no allocations allowed) ------------
__device__ int   g_ccount[NCELLS];
__device__ int   g_cstart[NCELLS + 1];
__device__ int   g_pcell[NPTS];
__device__ int   g_prank[NPTS];
__device__ __align__(16) float4 g_sorted[NPTS];   // (x, y, s, orig_id bits)
__device__ float g_mean[NPTS];

// ---------------- f32x2 packed helpers (sm_100+ PTX) ------------------------
__device__ __forceinline__ void ffma2(u64 &acc, u64 a, u64 b) {
    asm("fma.rn.f32x2 %0, %1, %2, %0;" : "+l"(acc) : "l"(a), "l"(b));
}
__device__ __forceinline__ u64 pack2(float x, float y) {
    u64 r; asm("mov.b64 %0, {%1, %2};" : "=l"(r) : "f"(x), "f"(y)); return r;
}
__device__ __forceinline__ void unpack2(u64 v, float &lo, float &hi) {
    asm("mov.b64 {%0, %1}, %2;" : "=f"(lo), "=f"(hi) : "l"(v));
}

// ---------------- grid build ------------------------------------------------
__global__ void zero_kernel() {
    int i = blockIdx.x * blockDim.x + threadIdx.x;
    if (i < NCELLS) g_ccount[i] = 0;
}

__device__ __forceinline__ int cell_of(float x, float y) {
    int cx = (int)floorf((x + LHALF) * INVH);
    int cy = (int)floorf((y + LHALF) * INVH);
    cx = min(GRID - 1, max(0, cx));
    cy = min(GRID - 1, max(0, cy));
    return cy * GRID + cx;
}

__global__ void cellid_kernel(const float* __restrict__ coords) {
    int i = blockIdx.x * blockDim.x + threadIdx.x;
    if (i < NPTS) {
        float x = coords[2 * i], y = coords[2 * i + 1];
        int c = cell_of(x, y);
        g_pcell[i] = c;
        g_prank[i] = atomicAdd(&g_ccount[c], 1);
    }
}

__global__ void __launch_bounds__(1024) scan_kernel() {
    __shared__ int part[1024];
    int tid = threadIdx.x;
    int base = tid * 36;
    int s = 0;
    #pragma unroll
    for (int k = 0; k < 36; k++) s += g_ccount[base + k];
    part[tid] = s;
    __syncthreads();
    for (int off = 1; off < 1024; off <<= 1) {
        int v = (tid >= off) ? part[tid - off] : 0;
        __syncthreads();
        part[tid] += v;
        __syncthreads();
    }
    int pre = (tid > 0) ? part[tid - 1] : 0;
    #pragma unroll
    for (int k = 0; k < 36; k++) {
        int cnt = g_ccount[base + k];
        g_cstart[base + k] = pre;
        pre += cnt;
    }
    if (tid == 1023) g_cstart[NCELLS] = pre;
}

__global__ void scatter_kernel(const float* __restrict__ coords) {
    int i = blockIdx.x * blockDim.x + threadIdx.x;
    if (i < NPTS) {
        float x = coords[2 * i], y = coords[2 * i + 1];
        float s = fmaf(x, x, y * y);
        int pos = g_cstart[g_pcell[i]] + g_prank[i];
        g_sorted[pos] = make_float4(x, y, s, __int_as_float(i));
    }
}

// deterministic order within each cell: insertion sort by original id
__global__ void sortcell_kernel() {
    int c = blockIdx.x * blockDim.x + threadIdx.x;
    if (c >= NCELLS) return;
    int beg = g_cstart[c], end = g_cstart[c + 1];
    for (int i = beg + 1; i < end; i++) {
        float4 v = g_sorted[i];
        int key = __float_as_int(v.w);
        int j = i - 1;
        while (j >= beg && __float_as_int(g_sorted[j].w) > key) {
            g_sorted[j + 1] = g_sorted[j];
            j--;
        }
        g_sorted[j + 1] = v;
    }
}

// ---------------- exact 7-NN via expanding rings ----------------------------
__device__ __forceinline__ void insert7(float d, float t[7], float &worst) {
    bool done = false;
    #pragma unroll
    for (int i = 0; i < 7; i++) {
        if (!done && t[i] == worst) { t[i] = d; done = true; }
    }
    float w = t[0];
    #pragma unroll
    for (int i = 1; i < 7; i++) w = fmaxf(w, t[i]);
    worst = w;
}

__device__ __forceinline__ void scan_run(int rowc, int x0, int x1,
                                         float a0, float a1,
                                         float t[7], float &worst) {
    int beg = g_cstart[rowc * GRID + x0];
    int end = g_cstart[rowc * GRID + x1 + 1];
    for (int idx = beg; idx < end; idx++) {
        float4 q = g_sorted[idx];
        float d = fmaf(a0, q.x, fmaf(a1, q.y, q.z));   // shifted d2 = d2 - s_p
        if (d < worst) insert7(d, t, worst);
    }
}

__global__ void __launch_bounds__(256) search_kernel() {
    int sp = blockIdx.x * blockDim.x + threadIdx.x;   // sorted position
    float4 p = g_sorted[sp];
    float px = p.x, py = p.y, si = p.z;
    int orig = __float_as_int(p.w);
    float a0 = -2.0f * px;
    float a1 = -2.0f * py;

    int cx = min(GRID - 1, max(0, (int)floorf((px + LHALF) * INVH)));
    int cy = min(GRID - 1, max(0, (int)floorf((py + LHALF) * INVH)));

    float t[7];
    #pragma unroll
    for (int i = 0; i < 7; i++) t[i] = FLT_MAX;
    float worst = FLT_MAX;

    // initial 3x3 block (rings 0 and 1)
    {
        int x0 = max(cx - 1, 0), x1 = min(cx + 1, GRID - 1);
        int y0 = max(cy - 1, 0), y1 = min(cy + 1, GRID - 1);
        for (int yy = y0; yy <= y1; yy++)
            scan_run(yy, x0, x1, a0, a1, t, worst);
    }

    int r = 1;
    while (true) {
        // stop check: any unscanned point lies outside the scanned rectangle;
        // sides at the grid edge are fully covered (clamped points live IN edge cells).
        float bound = 1e30f;
        bool anyside = false;
        if (cx - r >= 0)        { bound = fminf(bound, px - ((float)(cx - r) * HCELL - LHALF));       anyside = true; }
        if (cx + r <= GRID - 1) { bound = fminf(bound, ((float)(cx + r + 1) * HCELL - LHALF) - px);   anyside = true; }
        if (cy - r >= 0)        { bound = fminf(bound, py - ((float)(cy - r) * HCELL - LHALF));       anyside = true; }
        if (cy + r <= GRID - 1) { bound = fminf(bound, ((float)(cy + r + 1) * HCELL - LHALF) - py);   anyside = true; }
        if (!anyside) break;                                   // whole grid scanned: exact
        if (bound > 0.0f && worst + si <= bound * bound) break;  // 7-NN proven complete

        r++;
        int nx0 = max(cx - r, 0), nx1 = min(cx + r, GRID - 1);
        if (cy - r >= 0)        scan_run(cy - r, nx0, nx1, a0, a1, t, worst);
        if (cy + r <= GRID - 1) scan_run(cy + r, nx0, nx1, a0, a1, t, worst);
        int yy0 = max(cy - r + 1, 0), yy1 = min(cy + r - 1, GRID - 1);
        if (cx - r >= 0)
            for (int yy = yy0; yy <= yy1; yy++) scan_run(yy, cx - r, cx - r, a0, a1, t, worst);
        if (cx + r <= GRID - 1)
            for (int yy = yy0; yy <= yy1; yy++) scan_run(yy, cx + r, cx + r, a0, a1, t, worst);
    }

    // t[] = 7 smallest shifted-d2; self (= -si) is the minimum. Drop min, mean of 6 dists.
    float sum = 0.0f, mn = FLT_MAX;
    #pragma unroll
    for (int i = 0; i < 7; i++) {
        float dist = sqrtf(fmaxf(t[i] + si, 1e-12f));
        sum += dist;
        mn = fminf(mn, dist);
    }
    g_mean[orig] = (sum - mn) * (1.0f / 6.0f);
}

// -------- emb: out = silu(x@W1+b1)@W2+b2 + silu(m@Wd1+bd1)@Wd2+bd2 ----------
__global__ void __launch_bounds__(HDIM) emb_kernel(
    const float* __restrict__ coords,
    const float* __restrict__ W1,  const float* __restrict__ b1,
    const float* __restrict__ W2,  const float* __restrict__ b2,
    const float* __restrict__ Wd1, const float* __restrict__ bd1,
    const float* __restrict__ Wd2, const float* __restrict__ bd2,
    float* __restrict__ out)
{
    __shared__ __align__(16) float h1s[HDIM][TRP];   // 36 KB, [k][r]
    __shared__ __align__(16) float us[HD2][TRP];     // 18 KB, [k][r]
    __shared__ float2 xs[TR];
    __shared__ float  ms[TR];

    int j  = threadIdx.x;          // output column / hidden index
    int r0 = blockIdx.x * TR;      // first row of this block

    if (j < TR) {
        xs[j] = ((const float2*)coords)[r0 + j];
        ms[j] = g_mean[r0 + j];
    }
    __syncthreads();

    {
        float w1a = W1[j];
        float w1b = W1[HDIM + j];
        float bb  = b1[j];
        #pragma unroll
        for (int r = 0; r < TR; r++) {
            float h = fmaf(xs[r].x, w1a, fmaf(xs[r].y, w1b, bb));
            float sg = 1.0f / (1.0f + __expf(-h));
            h1s[j][r] = h * sg;
        }
    }
    if (j < HD2) {
        float w = Wd1[j];
        float b = bd1[j];
        #pragma unroll
        for (int r = 0; r < TR; r++) {
            float h = fmaf(ms[r], w, b);
            float sg = 1.0f / (1.0f + __expf(-h));
            us[j][r] = h * sg;
        }
    }
    __syncthreads();

    u64 acc[TR / 2];
    #pragma unroll
    for (int i = 0; i < TR / 2; i++) acc[i] = 0ull;

    #pragma unroll 2
    for (int k = 0; k < HDIM; k++) {
        float w  = W2[k * HDIM + j];
        u64  ww  = pack2(w, w);
        const ulonglong2* hp2 = (const ulonglong2*)&h1s[k][0];
        #pragma unroll
        for (int i = 0; i < TR / 4; i++) {
            ulonglong2 h2 = hp2[i];
            ffma2(acc[2 * i + 0], h2.x, ww);
            ffma2(acc[2 * i + 1], h2.y, ww);
        }
    }
    #pragma unroll 2
    for (int k = 0; k < HD2; k++) {
        float w  = Wd2[k * HDIM + j];
        u64  ww  = pack2(w, w);
        const ulonglong2* hp2 = (const ulonglong2*)&us[k][0];
        #pragma unroll
        for (int i = 0; i < TR / 4; i++) {
            ulonglong2 h2 = hp2[i];
            ffma2(acc[2 * i + 0], h2.x, ww);
            ffma2(acc[2 * i + 1], h2.y, ww);
        }
    }

    float bj = b2[j] + bd2[j];
    #pragma unroll
    for (int i = 0; i < TR / 2; i++) {
        float lo, hi;
        unpack2(acc[i], lo, hi);
        out[(r0 + 2 * i + 0) * HDIM + j] = lo + bj;
        out[(r0 + 2 * i + 1) * HDIM + j] = hi + bj;
    }
}

// ---------------- launch ----------------------------------------------------
extern "C" void kernel_launch(void* const* d_in, const int* in_sizes, int n_in,
                              void* d_out, int out_size)
{
    const float* coords = (const float*)d_in[0];
    const float* W1  = (const float*)d_in[1];
    const float* b1  = (const float*)d_in[2];
    const float* W2  = (const float*)d_in[3];
    const float* b2  = (const float*)d_in[4];
    const float* Wd1 = (const float*)d_in[5];
    const float* bd1 = (const float*)d_in[6];
    const float* Wd2 = (const float*)d_in[7];
    const float* bd2 = (const float*)d_in[8];
    float* out = (float*)d_out;

    zero_kernel<<<(NCELLS + 255) / 256, 256>>>();
    cellid_kernel<<<(NPTS + 255) / 256, 256>>>(coords);
    scan_kernel<<<1, 1024>>>();
    scatter_kernel<<<(NPTS + 255) / 256, 256>>>(coords);
    sortcell_kernel<<<(NCELLS + 255) / 256, 256>>>();
    search_kernel<<<NPTS / 256, 256>>>();
    emb_kernel<<<NPTS / TR, HDIM>>>(coords, W1, b1, W2, b2,
                                    Wd1, bd1, Wd2, bd2, out);
}

// round 11
// speedup vs baseline: 1.8952x; 1.8952x over previous
#include <cuda_runtime.h>
#include <math.h>
#include <float.h>

#define NPTS 16384
#define HDIM 256
#define HD2  128
#define TR   32          // rows per block in emb kernel
#define TRP  36          // padded row stride (floats), 16B-aligned
#define GRID 96
#define NCELLS (GRID * GRID)      // 9216 = 1024 * 9
#define HCELL 1.0f
#define INVH  1.0f
#define LHALF 48.0f

typedef unsigned long long u64;

// ---------------- static device scratch (no allocations allowed) ------------
__device__ int   g_ccount[NCELLS];
__device__ int   g_cstart[NCELLS + 1];
__device__ int   g_pcell[NPTS];
__device__ int   g_prank[NPTS];
__device__ __align__(16) float4 g_sorted[NPTS];   // (x, y, s, orig_id bits)
__device__ float g_mean[NPTS];

// ---------------- f32x2 packed helpers (sm_100+ PTX) ------------------------
__device__ __forceinline__ void ffma2(u64 &acc, u64 a, u64 b) {
    asm("fma.rn.f32x2 %0, %1, %2, %0;" : "+l"(acc) : "l"(a), "l"(b));
}
__device__ __forceinline__ u64 pack2(float x, float y) {
    u64 r; asm("mov.b64 %0, {%1, %2};" : "=l"(r) : "f"(x), "f"(y)); return r;
}
__device__ __forceinline__ void unpack2(u64 v, float &lo, float &hi) {
    asm("mov.b64 {%0, %1}, %2;" : "=f"(lo), "=f"(hi) : "l"(v));
}

// ---------------- grid build ------------------------------------------------
__global__ void zero_kernel() {
    int i = blockIdx.x * blockDim.x + threadIdx.x;
    if (i < NCELLS) g_ccount[i] = 0;
}

__device__ __forceinline__ int cell_of(float x, float y) {
    int cx = (int)floorf((x + LHALF) * INVH);
    int cy = (int)floorf((y + LHALF) * INVH);
    cx = min(GRID - 1, max(0, cx));
    cy = min(GRID - 1, max(0, cy));
    return cy * GRID + cx;
}

__global__ void cellid_kernel(const float* __restrict__ coords) {
    int i = blockIdx.x * blockDim.x + threadIdx.x;
    if (i < NPTS) {
        float x = coords[2 * i], y = coords[2 * i + 1];
        int c = cell_of(x, y);
        g_pcell[i] = c;
        g_prank[i] = atomicAdd(&g_ccount[c], 1);
    }
}

__global__ void __launch_bounds__(1024) scan_kernel() {
    __shared__ int part[1024];
    int tid = threadIdx.x;
    int base = tid * 9;
    int s = 0;
    #pragma unroll
    for (int k = 0; k < 9; k++) s += g_ccount[base + k];
    part[tid] = s;
    __syncthreads();
    for (int off = 1; off < 1024; off <<= 1) {
        int v = (tid >= off) ? part[tid - off] : 0;
        __syncthreads();
        part[tid] += v;
        __syncthreads();
    }
    int pre = (tid > 0) ? part[tid - 1] : 0;
    #pragma unroll
    for (int k = 0; k < 9; k++) {
        int cnt = g_ccount[base + k];
        g_cstart[base + k] = pre;
        pre += cnt;
    }
    if (tid == 1023) g_cstart[NCELLS] = pre;
}

__global__ void scatter_kernel(const float* __restrict__ coords) {
    int i = blockIdx.x * blockDim.x + threadIdx.x;
    if (i < NPTS) {
        float x = coords[2 * i], y = coords[2 * i + 1];
        float s = fmaf(x, x, y * y);
        int pos = g_cstart[g_pcell[i]] + g_prank[i];
        g_sorted[pos] = make_float4(x, y, s, __int_as_float(i));
    }
}

// ---------------- warp-cooperative exact 7-NN -------------------------------
__device__ __forceinline__ void insert7(float d, float t[7], float &worst) {
    bool done = false;
    #pragma unroll
    for (int i = 0; i < 7; i++) {
        if (!done && t[i] == worst) { t[i] = d; done = true; }
    }
    float w = t[0];
    #pragma unroll
    for (int i = 1; i < 7; i++) w = fmaxf(w, t[i]);
    worst = w;
}

// lanes split candidates of a contiguous cell run [x0..x1] in grid row rowc
__device__ __forceinline__ void scan_run_warp(int rowc, int x0, int x1, int lane,
                                              float a0, float a1,
                                              float t[7], float &worst) {
    int beg = g_cstart[rowc * GRID + x0];
    int end = g_cstart[rowc * GRID + x1 + 1];
    for (int idx = beg + lane; idx < end; idx += 32) {
        float4 q = g_sorted[idx];
        float d = fmaf(a0, q.x, fmaf(a1, q.y, q.z));   // shifted d2 = d2 - s_p
        if (d < worst) insert7(d, t, worst);
    }
}

// non-destructive merge of 32 per-lane top-7 lists -> sorted 7 smallest (all lanes)
__device__ __forceinline__ void warp_merge7(const float t[7], int lane, float w[7]) {
    float v[7];
    #pragma unroll
    for (int i = 0; i < 7; i++) v[i] = t[i];
    #pragma unroll
    for (int it = 0; it < 7; it++) {
        float lm = v[0];
        #pragma unroll
        for (int i = 1; i < 7; i++) lm = fminf(lm, v[i]);
        float m = lm;
        #pragma unroll
        for (int off = 16; off > 0; off >>= 1)
            m = fminf(m, __shfl_xor_sync(0xffffffffu, m, off));
        unsigned msk = __ballot_sync(0xffffffffu, lm == m);
        int src = __ffs(msk) - 1;
        if (lane == src) {
            bool done = false;
            #pragma unroll
            for (int i = 0; i < 7; i++)
                if (!done && v[i] == m) { v[i] = FLT_MAX; done = true; }
        }
        w[it] = m;
    }
}

__global__ void __launch_bounds__(256) search_kernel() {
    int lane = threadIdx.x & 31;
    int sp   = blockIdx.x * 8 + (threadIdx.x >> 5);   // one warp per sorted point

    float4 p = g_sorted[sp];
    float px = p.x, py = p.y, si = p.z;
    int orig = __float_as_int(p.w);
    float a0 = -2.0f * px;
    float a1 = -2.0f * py;

    int cx = min(GRID - 1, max(0, (int)floorf((px + LHALF) * INVH)));
    int cy = min(GRID - 1, max(0, (int)floorf((py + LHALF) * INVH)));

    float t[7];
    #pragma unroll
    for (int i = 0; i < 7; i++) t[i] = FLT_MAX;
    float worst = FLT_MAX;

    // initial 3x3 block (rings 0 and 1)
    {
        int x0 = max(cx - 1, 0), x1 = min(cx + 1, GRID - 1);
        int y0 = max(cy - 1, 0), y1 = min(cy + 1, GRID - 1);
        for (int yy = y0; yy <= y1; yy++)
            scan_run_warp(yy, x0, x1, lane, a0, a1, t, worst);
    }

    float w[7];
    int r = 1;
    while (true) {
        warp_merge7(t, lane, w);
        float wu = w[6];                               // union 7th-best (shifted)

        // stop check: sides at the grid edge are fully covered (clamped points
        // live IN edge cells); otherwise bound by distance to unscanned region.
        float bound = 1e30f;
        bool anyside = false;
        if (cx - r >= 0)        { bound = fminf(bound, px - ((float)(cx - r) * HCELL - LHALF));       anyside = true; }
        if (cx + r <= GRID - 1) { bound = fminf(bound, ((float)(cx + r + 1) * HCELL - LHALF) - px);   anyside = true; }
        if (cy - r >= 0)        { bound = fminf(bound, py - ((float)(cy - r) * HCELL - LHALF));       anyside = true; }
        if (cy + r <= GRID - 1) { bound = fminf(bound, ((float)(cy + r + 1) * HCELL - LHALF) - py);   anyside = true; }
        if (!anyside) break;                                    // whole grid scanned
        if (bound > 0.0f && wu + si <= bound * bound) break;    // 7-NN proven complete

        r++;
        int nx0 = max(cx - r, 0), nx1 = min(cx + r, GRID - 1);
        if (cy - r >= 0)        scan_run_warp(cy - r, nx0, nx1, lane, a0, a1, t, worst);
        if (cy + r <= GRID - 1) scan_run_warp(cy + r, nx0, nx1, lane, a0, a1, t, worst);
        int yy0 = max(cy - r + 1, 0), yy1 = min(cy + r - 1, GRID - 1);
        if (cx - r >= 0)
            for (int yy = yy0; yy <= yy1; yy++) scan_run_warp(yy, cx - r, cx - r, lane, a0, a1, t, worst);
        if (cx + r <= GRID - 1)
            for (int yy = yy0; yy <= yy1; yy++) scan_run_warp(yy, cx + r, cx + r, lane, a0, a1, t, worst);
    }

    // w[0..6] ascending; w[0] = self (= -si). Mean of the 6 non-self distances.
    if (lane == 0) {
        float sum = 0.0f;
        #pragma unroll
        for (int i = 1; i < 7; i++)
            sum += sqrtf(fmaxf(w[i] + si, 1e-12f));
        g_mean[orig] = sum * (1.0f / 6.0f);
    }
}

// -------- emb: out = silu(x@W1+b1)@W2+b2 + silu(m@Wd1+bd1)@Wd2+bd2 ----------
__global__ void __launch_bounds__(HDIM) emb_kernel(
    const float* __restrict__ coords,
    const float* __restrict__ W1,  const float* __restrict__ b1,
    const float* __restrict__ W2,  const float* __restrict__ b2,
    const float* __restrict__ Wd1, const float* __restrict__ bd1,
    const float* __restrict__ Wd2, const float* __restrict__ bd2,
    float* __restrict__ out)
{
    __shared__ __align__(16) float h1s[HDIM][TRP];   // 36 KB, [k][r]
    __shared__ __align__(16) float us[HD2][TRP];     // 18 KB, [k][r]
    __shared__ float2 xs[TR];
    __shared__ float  ms[TR];

    int j  = threadIdx.x;          // output column / hidden index
    int r0 = blockIdx.x * TR;      // first row of this block

    if (j < TR) {
        xs[j] = ((const float2*)coords)[r0 + j];
        ms[j] = g_mean[r0 + j];
    }
    __syncthreads();

    {
        float w1a = W1[j];
        float w1b = W1[HDIM + j];
        float bb  = b1[j];
        #pragma unroll
        for (int r = 0; r < TR; r++) {
            float h = fmaf(xs[r].x, w1a, fmaf(xs[r].y, w1b, bb));
            float sg = 1.0f / (1.0f + __expf(-h));
            h1s[j][r] = h * sg;
        }
    }
    if (j < HD2) {
        float w = Wd1[j];
        float b = bd1[j];
        #pragma unroll
        for (int r = 0; r < TR; r++) {
            float h = fmaf(ms[r], w, b);
            float sg = 1.0f / (1.0f + __expf(-h));
            us[j][r] = h * sg;
        }
    }
    __syncthreads();

    u64 acc[TR / 2];
    #pragma unroll
    for (int i = 0; i < TR / 2; i++) acc[i] = 0ull;

    #pragma unroll 2
    for (int k = 0; k < HDIM; k++) {
        float w  = W2[k * HDIM + j];
        u64  ww  = pack2(w, w);
        const ulonglong2* hp2 = (const ulonglong2*)&h1s[k][0];
        #pragma unroll
        for (int i = 0; i < TR / 4; i++) {
            ulonglong2 h2 = hp2[i];
            ffma2(acc[2 * i + 0], h2.x, ww);
            ffma2(acc[2 * i + 1], h2.y, ww);
        }
    }
    #pragma unroll 2
    for (int k = 0; k < HD2; k++) {
        float w  = Wd2[k * HDIM + j];
        u64  ww  = pack2(w, w);
        const ulonglong2* hp2 = (const ulonglong2*)&us[k][0];
        #pragma unroll
        for (int i = 0; i < TR / 4; i++) {
            ulonglong2 h2 = hp2[i];
            ffma2(acc[2 * i + 0], h2.x, ww);
            ffma2(acc[2 * i + 1], h2.y, ww);
        }
    }

    float bj = b2[j] + bd2[j];
    #pragma unroll
    for (int i = 0; i < TR / 2; i++) {
        float lo, hi;
        unpack2(acc[i], lo, hi);
        out[(r0 + 2 * i + 0) * HDIM + j] = lo + bj;
        out[(r0 + 2 * i + 1) * HDIM + j] = hi + bj;
    }
}

// ---------------- launch ----------------------------------------------------
extern "C" void kernel_launch(void* const* d_in, const int* in_sizes, int n_in,
                              void* d_out, int out_size)
{
    const float* coords = (const float*)d_in[0];
    const float* W1  = (const float*)d_in[1];
    const float* b1  = (const float*)d_in[2];
    const float* W2  = (const float*)d_in[3];
    const float* b2  = (const float*)d_in[4];
    const float* Wd1 = (const float*)d_in[5];
    const float* bd1 = (const float*)d_in[6];
    const float* Wd2 = (const float*)d_in[7];
    const float* bd2 = (const float*)d_in[8];
    float* out = (float*)d_out;

    zero_kernel<<<(NCELLS + 255) / 256, 256>>>();
    cellid_kernel<<<(NPTS + 255) / 256, 256>>>(coords);
    scan_kernel<<<1, 1024>>>();
    scatter_kernel<<<(NPTS + 255) / 256, 256>>>(coords);
    search_kernel<<<NPTS / 8, 256>>>();
    emb_kernel<<<NPTS / TR, HDIM>>>(coords, W1, b1, W2, b2,
                                    Wd1, bd1, Wd2, bd2, out);
}

// round 12
// speedup vs baseline: 2.3572x; 1.2438x over previous
#include <cuda_runtime.h>
#include <math.h>
#include <float.h>

#define NPTS 16384
#define HDIM 256
#define HD2  128
#define TR   32          // rows per block in emb kernel
#define TRP  36          // padded row stride (floats), 16B-aligned
#define GRID 96
#define NCELLS (GRID * GRID)      // 9216 = 1024 * 9
#define HCELL 1.0f
#define INVH  1.0f
#define LHALF 48.0f

typedef unsigned long long u64;

// ---------------- static device scratch (no allocations allowed) ------------
__device__ int   g_ccount[NCELLS];
__device__ int   g_cstart[NCELLS + 1];
__device__ int   g_pcell[NPTS];
__device__ int   g_prank[NPTS];
__device__ __align__(16) float4 g_sorted[NPTS];   // (x, y, s, orig_id bits)
__device__ float g_mean[NPTS];

// ---------------- f32x2 packed helpers (sm_100+ PTX) ------------------------
__device__ __forceinline__ void ffma2(u64 &acc, u64 a, u64 b) {
    asm("fma.rn.f32x2 %0, %1, %2, %0;" : "+l"(acc) : "l"(a), "l"(b));
}
__device__ __forceinline__ u64 pack2(float x, float y) {
    u64 r; asm("mov.b64 %0, {%1, %2};" : "=l"(r) : "f"(x), "f"(y)); return r;
}
__device__ __forceinline__ void unpack2(u64 v, float &lo, float &hi) {
    asm("mov.b64 {%0, %1}, %2;" : "=f"(lo), "=f"(hi) : "l"(v));
}

// ---------------- grid build ------------------------------------------------
__global__ void zero_kernel() {
    int i = blockIdx.x * blockDim.x + threadIdx.x;
    if (i < NCELLS) g_ccount[i] = 0;
}

__device__ __forceinline__ int cell_of(float x, float y) {
    int cx = (int)floorf((x + LHALF) * INVH);
    int cy = (int)floorf((y + LHALF) * INVH);
    cx = min(GRID - 1, max(0, cx));
    cy = min(GRID - 1, max(0, cy));
    return cy * GRID + cx;
}

__global__ void cellid_kernel(const float* __restrict__ coords) {
    int i = blockIdx.x * blockDim.x + threadIdx.x;
    if (i < NPTS) {
        float x = coords[2 * i], y = coords[2 * i + 1];
        int c = cell_of(x, y);
        g_pcell[i] = c;
        g_prank[i] = atomicAdd(&g_ccount[c], 1);
    }
}

__global__ void __launch_bounds__(1024) scan_kernel() {
    __shared__ int part[1024];
    int tid = threadIdx.x;
    int base = tid * 9;
    int s = 0;
    #pragma unroll
    for (int k = 0; k < 9; k++) s += g_ccount[base + k];
    part[tid] = s;
    __syncthreads();
    for (int off = 1; off < 1024; off <<= 1) {
        int v = (tid >= off) ? part[tid - off] : 0;
        __syncthreads();
        part[tid] += v;
        __syncthreads();
    }
    int pre = (tid > 0) ? part[tid - 1] : 0;
    #pragma unroll
    for (int k = 0; k < 9; k++) {
        int cnt = g_ccount[base + k];
        g_cstart[base + k] = pre;
        pre += cnt;
    }
    if (tid == 1023) g_cstart[NCELLS] = pre;
}

__global__ void scatter_kernel(const float* __restrict__ coords) {
    int i = blockIdx.x * blockDim.x + threadIdx.x;
    if (i < NPTS) {
        float x = coords[2 * i], y = coords[2 * i + 1];
        float s = fmaf(x, x, y * y);
        int pos = g_cstart[g_pcell[i]] + g_prank[i];
        g_sorted[pos] = make_float4(x, y, s, __int_as_float(i));
    }
}

// ---------------- warp-cooperative exact 7-NN (two-phase) -------------------
__device__ __forceinline__ void insert7(float d, float t[7], float &worst) {
    bool done = false;
    #pragma unroll
    for (int i = 0; i < 7; i++) {
        if (!done && t[i] == worst) { t[i] = d; done = true; }
    }
    float w = t[0];
    #pragma unroll
    for (int i = 1; i < 7; i++) w = fmaxf(w, t[i]);
    worst = w;
}

// scan all cells in rect rows [y0..y1] x cols [x0..x1] (already clamped or
// empty); per 32-row chunk, lanes load row begin/end in ONE parallel wave,
// then rows are processed with shfl-distributed bounds and lane-split
// candidate loops (coalesced float4 loads).
__device__ __forceinline__ void scan_rect(int y0, int y1, int x0, int x1,
                                          int lane, float a0, float a1,
                                          float t[7], float &worst) {
    if (y0 > y1 || x0 > x1) return;
    for (int yb = y0; yb <= y1; yb += 32) {
        int y = yb + lane;
        int rb = 0, re = 0;
        if (y <= y1) {
            rb = g_cstart[y * GRID + x0];
            re = g_cstart[y * GRID + x1 + 1];
        }
        int nrows = min(32, y1 - yb + 1);
        for (int k = 0; k < nrows; k++) {
            int b = __shfl_sync(0xffffffffu, rb, k);
            int e = __shfl_sync(0xffffffffu, re, k);
            for (int idx = b + lane; idx < e; idx += 32) {
                float4 q = g_sorted[idx];
                float d = fmaf(a0, q.x, fmaf(a1, q.y, q.z));   // d2 - s_p
                if (d < worst) insert7(d, t, worst);
            }
        }
    }
}

// non-destructive merge of 32 per-lane top-7 lists -> sorted 7 smallest (all lanes)
__device__ __forceinline__ void warp_merge7(const float t[7], int lane, float w[7]) {
    float v[7];
    #pragma unroll
    for (int i = 0; i < 7; i++) v[i] = t[i];
    #pragma unroll
    for (int it = 0; it < 7; it++) {
        float lm = v[0];
        #pragma unroll
        for (int i = 1; i < 7; i++) lm = fminf(lm, v[i]);
        float m = lm;
        #pragma unroll
        for (int off = 16; off > 0; off >>= 1)
            m = fminf(m, __shfl_xor_sync(0xffffffffu, m, off));
        unsigned msk = __ballot_sync(0xffffffffu, lm == m);
        int src = __ffs(msk) - 1;
        if (lane == src) {
            bool done = false;
            #pragma unroll
            for (int i = 0; i < 7; i++)
                if (!done && v[i] == m) { v[i] = FLT_MAX; done = true; }
        }
        w[it] = m;
    }
}

__global__ void __launch_bounds__(256) search_kernel() {
    int lane = threadIdx.x & 31;
    int sp   = blockIdx.x * 8 + (threadIdx.x >> 5);   // one warp per sorted point

    float4 p = g_sorted[sp];
    float px = p.x, py = p.y, si = p.z;
    int orig = __float_as_int(p.w);
    float a0 = -2.0f * px;
    float a1 = -2.0f * py;

    int cx = min(GRID - 1, max(0, (int)floorf((px + LHALF) * INVH)));
    int cy = min(GRID - 1, max(0, (int)floorf((py + LHALF) * INVH)));

    // ---- Phase A: smallest box radius R containing >= 8 points (counts only)
    int R = 1;
    while (true) {
        int y0 = max(cy - R, 0), y1 = min(cy + R, GRID - 1);
        int x0 = max(cx - R, 0), x1 = min(cx + R, GRID - 1);
        int cnt = 0;
        for (int yb = y0; yb <= y1; yb += 32) {
            int y = yb + lane;
            int c = 0;
            if (y <= y1)
                c = g_cstart[y * GRID + x1 + 1] - g_cstart[y * GRID + x0];
            #pragma unroll
            for (int off = 16; off > 0; off >>= 1)
                c += __shfl_xor_sync(0xffffffffu, c, off);
            cnt += c;
        }
        bool full = (y0 == 0 && y1 == GRID - 1 && x0 == 0 && x1 == GRID - 1);
        if (cnt >= 8 || full) break;
        R++;
    }

    // ---- Phase B: scan box(R)
    float t[7];
    #pragma unroll
    for (int i = 0; i < 7; i++) t[i] = FLT_MAX;
    float worst = FLT_MAX;
    {
        int y0 = max(cy - R, 0), y1 = min(cy + R, GRID - 1);
        int x0 = max(cx - R, 0), x1 = min(cx + R, GRID - 1);
        scan_rect(y0, y1, x0, x1, lane, a0, a1, t, worst);
    }

    // ---- Phase C: safe radius from merged 7th-best, one annulus scan
    float w[7];
    warp_merge7(t, lane, w);
    float wu = w[6];                                   // 7th-best shifted d2
    // dist from p to box(Rf) edge >= Rf*HCELL on every non-clamped side;
    // clamped sides are fully covered (outliers live in edge cells).
    int Rf = (int)(sqrtf(fmaxf(wu + si, 0.0f)) * INVH) + 1;   // strict round-up
    if (Rf > R) {
        int X0 = max(cx - Rf, 0), X1 = min(cx + Rf, GRID - 1);
        int yo0 = max(cy - R, 0), yo1 = min(cy + R, GRID - 1);
        // top / bottom full-width blocks (guards inside scan_rect)
        scan_rect(max(cy - Rf, 0), cy - R - 1, X0, X1, lane, a0, a1, t, worst);
        scan_rect(cy + R + 1, min(cy + Rf, GRID - 1), X0, X1, lane, a0, a1, t, worst);
        // left / right side strips on the middle rows
        scan_rect(yo0, yo1, X0, cx - R - 1, lane, a0, a1, t, worst);
        scan_rect(yo0, yo1, cx + R + 1, X1, lane, a0, a1, t, worst);
        warp_merge7(t, lane, w);
    }

    // w[0..6] ascending; w[0] = self (= -si). Mean of the 6 non-self distances.
    if (lane == 0) {
        float sum = 0.0f;
        #pragma unroll
        for (int i = 1; i < 7; i++)
            sum += sqrtf(fmaxf(w[i] + si, 1e-12f));
        g_mean[orig] = sum * (1.0f / 6.0f);
    }
}

// -------- emb: out = silu(x@W1+b1)@W2+b2 + silu(m@Wd1+bd1)@Wd2+bd2 ----------
__global__ void __launch_bounds__(HDIM) emb_kernel(
    const float* __restrict__ coords,
    const float* __restrict__ W1,  const float* __restrict__ b1,
    const float* __restrict__ W2,  const float* __restrict__ b2,
    const float* __restrict__ Wd1, const float* __restrict__ bd1,
    const float* __restrict__ Wd2, const float* __restrict__ bd2,
    float* __restrict__ out)
{
    __shared__ __align__(16) float h1s[HDIM][TRP];   // 36 KB, [k][r]
    __shared__ __align__(16) float us[HD2][TRP];     // 18 KB, [k][r]
    __shared__ float2 xs[TR];
    __shared__ float  ms[TR];

    int j  = threadIdx.x;          // output column / hidden index
    int r0 = blockIdx.x * TR;      // first row of this block

    if (j < TR) {
        xs[j] = ((const float2*)coords)[r0 + j];
        ms[j] = g_mean[r0 + j];
    }
    __syncthreads();

    {
        float w1a = W1[j];
        float w1b = W1[HDIM + j];
        float bb  = b1[j];
        #pragma unroll
        for (int r = 0; r < TR; r++) {
            float h = fmaf(xs[r].x, w1a, fmaf(xs[r].y, w1b, bb));
            float sg = 1.0f / (1.0f + __expf(-h));
            h1s[j][r] = h * sg;
        }
    }
    if (j < HD2) {
        float w = Wd1[j];
        float b = bd1[j];
        #pragma unroll
        for (int r = 0; r < TR; r++) {
            float h = fmaf(ms[r], w, b);
            float sg = 1.0f / (1.0f + __expf(-h));
            us[j][r] = h * sg;
        }
    }
    __syncthreads();

    u64 acc[TR / 2];
    #pragma unroll
    for (int i = 0; i < TR / 2; i++) acc[i] = 0ull;

    #pragma unroll 2
    for (int k = 0; k < HDIM; k++) {
        float w  = W2[k * HDIM + j];
        u64  ww  = pack2(w, w);
        const ulonglong2* hp2 = (const ulonglong2*)&h1s[k][0];
        #pragma unroll
        for (int i = 0; i < TR / 4; i++) {
            ulonglong2 h2 = hp2[i];
            ffma2(acc[2 * i + 0], h2.x, ww);
            ffma2(acc[2 * i + 1], h2.y, ww);
        }
    }
    #pragma unroll 2
    for (int k = 0; k < HD2; k++) {
        float w  = Wd2[k * HDIM + j];
        u64  ww  = pack2(w, w);
        const ulonglong2* hp2 = (const ulonglong2*)&us[k][0];
        #pragma unroll
        for (int i = 0; i < TR / 4; i++) {
            ulonglong2 h2 = hp2[i];
            ffma2(acc[2 * i + 0], h2.x, ww);
            ffma2(acc[2 * i + 1], h2.y, ww);
        }
    }

    float bj = b2[j] + bd2[j];
    #pragma unroll
    for (int i = 0; i < TR / 2; i++) {
        float lo, hi;
        unpack2(acc[i], lo, hi);
        out[(r0 + 2 * i + 0) * HDIM + j] = lo + bj;
        out[(r0 + 2 * i + 1) * HDIM + j] = hi + bj;
    }
}

// ---------------- launch ----------------------------------------------------
extern "C" void kernel_launch(void* const* d_in, const int* in_sizes, int n_in,
                              void* d_out, int out_size)
{
    const float* coords = (const float*)d_in[0];
    const float* W1  = (const float*)d_in[1];
    const float* b1  = (const float*)d_in[2];
    const float* W2  = (const float*)d_in[3];
    const float* b2  = (const float*)d_in[4];
    const float* Wd1 = (const float*)d_in[5];
    const float* bd1 = (const float*)d_in[6];
    const float* Wd2 = (const float*)d_in[7];
    const float* bd2 = (const float*)d_in[8];
    float* out = (float*)d_out;

    zero_kernel<<<(NCELLS + 255) / 256, 256>>>();
    cellid_kernel<<<(NPTS + 255) / 256, 256>>>(coords);
    scan_kernel<<<1, 1024>>>();
    scatter_kernel<<<(NPTS + 255) / 256, 256>>>(coords);
    search_kernel<<<NPTS / 8, 256>>>();
    emb_kernel<<<NPTS / TR, HDIM>>>(coords, W1, b1, W2, b2,
                                    Wd1, bd1, Wd2, bd2, out);
}

// round 13
// speedup vs baseline: 4.5253x; 1.9198x over previous
#include <cuda_runtime.h>
#include <math.h>
#include <float.h>

#define NPTS 16384
#define HDIM 256
#define HD2  128
#define GRID 96
#define NCELLS (GRID * GRID)
#define HCELL 1.0f
#define INVH  1.0f
#define LHALF 48.0f

#define RB   64          // rows per emb block
#define KC   32          // K-chunk staged in smem
#define KTOT 384         // 256 (W2) + 128 (Wd2)
#define ASTR 36          // Asm row stride (words) — banks 4g+t conflict-free
#define BSTR 264         // Bsm row stride (words) — banks 8t+g conflict-free

typedef unsigned int u32;

// ---------------- static device scratch (no allocations allowed) ------------
__device__ int   g_ccount[NCELLS];
__device__ int   g_cstart[NCELLS + 1];
__device__ int   g_pcell[NPTS];
__device__ int   g_prank[NPTS];
__device__ __align__(16) float4 g_sorted[NPTS];   // (x, y, s, orig_id bits)
__device__ float g_mean[NPTS];

// ---------------- tf32 mma helpers ------------------------------------------
__device__ __forceinline__ u32 f2tf32(float f) {
    u32 r; asm("cvt.rna.tf32.f32 %0, %1;" : "=r"(r) : "f"(f)); return r;
}
__device__ __forceinline__ void mma_tf32(float c[4], u32 a0, u32 a1, u32 a2, u32 a3,
                                         u32 b0, u32 b1) {
    asm volatile(
        "mma.sync.aligned.m16n8k8.row.col.f32.tf32.tf32.f32 "
        "{%0,%1,%2,%3}, {%4,%5,%6,%7}, {%8,%9}, {%0,%1,%2,%3};"
        : "+f"(c[0]), "+f"(c[1]), "+f"(c[2]), "+f"(c[3])
        : "r"(a0), "r"(a1), "r"(a2), "r"(a3), "r"(b0), "r"(b1));
}

// ---------------- grid build ------------------------------------------------
__global__ void zero_kernel() {
    int i = blockIdx.x * blockDim.x + threadIdx.x;
    if (i < NCELLS) g_ccount[i] = 0;
}

__device__ __forceinline__ int cell_of(float x, float y) {
    int cx = (int)floorf((x + LHALF) * INVH);
    int cy = (int)floorf((y + LHALF) * INVH);
    cx = min(GRID - 1, max(0, cx));
    cy = min(GRID - 1, max(0, cy));
    return cy * GRID + cx;
}

__global__ void cellid_kernel(const float* __restrict__ coords) {
    int i = blockIdx.x * blockDim.x + threadIdx.x;
    if (i < NPTS) {
        float x = coords[2 * i], y = coords[2 * i + 1];
        int c = cell_of(x, y);
        g_pcell[i] = c;
        g_prank[i] = atomicAdd(&g_ccount[c], 1);
    }
}

__global__ void __launch_bounds__(1024) scan_kernel() {
    __shared__ int part[1024];
    int tid = threadIdx.x;
    int base = tid * 9;
    int s = 0;
    #pragma unroll
    for (int k = 0; k < 9; k++) s += g_ccount[base + k];
    part[tid] = s;
    __syncthreads();
    for (int off = 1; off < 1024; off <<= 1) {
        int v = (tid >= off) ? part[tid - off] : 0;
        __syncthreads();
        part[tid] += v;
        __syncthreads();
    }
    int pre = (tid > 0) ? part[tid - 1] : 0;
    #pragma unroll
    for (int k = 0; k < 9; k++) {
        int cnt = g_ccount[base + k];
        g_cstart[base + k] = pre;
        pre += cnt;
    }
    if (tid == 1023) g_cstart[NCELLS] = pre;
}

__global__ void scatter_kernel(const float* __restrict__ coords) {
    int i = blockIdx.x * blockDim.x + threadIdx.x;
    if (i < NPTS) {
        float x = coords[2 * i], y = coords[2 * i + 1];
        float s = fmaf(x, x, y * y);
        int pos = g_cstart[g_pcell[i]] + g_prank[i];
        g_sorted[pos] = make_float4(x, y, s, __int_as_float(i));
    }
}

// ---------------- warp-cooperative exact 7-NN (two-phase) -------------------
__device__ __forceinline__ void insert7(float d, float t[7], float &worst) {
    bool done = false;
    #pragma unroll
    for (int i = 0; i < 7; i++) {
        if (!done && t[i] == worst) { t[i] = d; done = true; }
    }
    float w = t[0];
    #pragma unroll
    for (int i = 1; i < 7; i++) w = fmaxf(w, t[i]);
    worst = w;
}

__device__ __forceinline__ void scan_rect(int y0, int y1, int x0, int x1,
                                          int lane, float a0, float a1,
                                          float t[7], float &worst) {
    if (y0 > y1 || x0 > x1) return;
    for (int yb = y0; yb <= y1; yb += 32) {
        int y = yb + lane;
        int rb = 0, re = 0;
        if (y <= y1) {
            rb = g_cstart[y * GRID + x0];
            re = g_cstart[y * GRID + x1 + 1];
        }
        int nrows = min(32, y1 - yb + 1);
        for (int k = 0; k < nrows; k++) {
            int b = __shfl_sync(0xffffffffu, rb, k);
            int e = __shfl_sync(0xffffffffu, re, k);
            for (int idx = b + lane; idx < e; idx += 32) {
                float4 q = g_sorted[idx];
                float d = fmaf(a0, q.x, fmaf(a1, q.y, q.z));   // d2 - s_p
                if (d < worst) insert7(d, t, worst);
            }
        }
    }
}

__device__ __forceinline__ void warp_merge7(const float t[7], int lane, float w[7]) {
    float v[7];
    #pragma unroll
    for (int i = 0; i < 7; i++) v[i] = t[i];
    #pragma unroll
    for (int it = 0; it < 7; it++) {
        float lm = v[0];
        #pragma unroll
        for (int i = 1; i < 7; i++) lm = fminf(lm, v[i]);
        float m = lm;
        #pragma unroll
        for (int off = 16; off > 0; off >>= 1)
            m = fminf(m, __shfl_xor_sync(0xffffffffu, m, off));
        unsigned msk = __ballot_sync(0xffffffffu, lm == m);
        int src = __ffs(msk) - 1;
        if (lane == src) {
            bool done = false;
            #pragma unroll
            for (int i = 0; i < 7; i++)
                if (!done && v[i] == m) { v[i] = FLT_MAX; done = true; }
        }
        w[it] = m;
    }
}

__global__ void __launch_bounds__(256) search_kernel() {
    int lane = threadIdx.x & 31;
    int sp   = blockIdx.x * 8 + (threadIdx.x >> 5);   // one warp per sorted point

    float4 p = g_sorted[sp];
    float px = p.x, py = p.y, si = p.z;
    int orig = __float_as_int(p.w);
    float a0 = -2.0f * px;
    float a1 = -2.0f * py;

    int cx = min(GRID - 1, max(0, (int)floorf((px + LHALF) * INVH)));
    int cy = min(GRID - 1, max(0, (int)floorf((py + LHALF) * INVH)));

    // Phase A: smallest (geometric) box radius R with >= 8 points, counts only
    int R = 1;
    while (true) {
        int y0 = max(cy - R, 0), y1 = min(cy + R, GRID - 1);
        int x0 = max(cx - R, 0), x1 = min(cx + R, GRID - 1);
        int cnt = 0;
        for (int yb = y0; yb <= y1; yb += 32) {
            int y = yb + lane;
            int c = 0;
            if (y <= y1)
                c = g_cstart[y * GRID + x1 + 1] - g_cstart[y * GRID + x0];
            #pragma unroll
            for (int off = 16; off > 0; off >>= 1)
                c += __shfl_xor_sync(0xffffffffu, c, off);
            cnt += c;
        }
        bool full = (y0 == 0 && y1 == GRID - 1 && x0 == 0 && x1 == GRID - 1);
        if (cnt >= 8 || full) break;
        R <<= 1;                                   // geometric expansion
    }

    // Phase B: scan box(R)
    float t[7];
    #pragma unroll
    for (int i = 0; i < 7; i++) t[i] = FLT_MAX;
    float worst = FLT_MAX;
    {
        int y0 = max(cy - R, 0), y1 = min(cy + R, GRID - 1);
        int x0 = max(cx - R, 0), x1 = min(cx + R, GRID - 1);
        scan_rect(y0, y1, x0, x1, lane, a0, a1, t, worst);
    }

    // Phase C: safe radius from merged 7th-best, one annulus scan
    float w[7];
    warp_merge7(t, lane, w);
    float wu = w[6];
    int Rf = (int)(sqrtf(fmaxf(wu + si, 0.0f)) * INVH) + 1;   // strict round-up
    if (Rf > R) {
        int X0 = max(cx - Rf, 0), X1 = min(cx + Rf, GRID - 1);
        int yo0 = max(cy - R, 0), yo1 = min(cy + R, GRID - 1);
        scan_rect(max(cy - Rf, 0), cy - R - 1, X0, X1, lane, a0, a1, t, worst);
        scan_rect(cy + R + 1, min(cy + Rf, GRID - 1), X0, X1, lane, a0, a1, t, worst);
        scan_rect(yo0, yo1, X0, cx - R - 1, lane, a0, a1, t, worst);
        scan_rect(yo0, yo1, cx + R + 1, X1, lane, a0, a1, t, worst);
        warp_merge7(t, lane, w);
    }

    if (lane == 0) {
        float sum = 0.0f;
        #pragma unroll
        for (int i = 1; i < 7; i++)
            sum += sqrtf(fmaxf(w[i] + si, 1e-12f));
        g_mean[orig] = sum * (1.0f / 6.0f);
    }
}

// -------- emb via tf32 mma.sync: out = silu(x@W1+b1)@W2 + silu(m@Wd1+bd1)@Wd2 + b2+bd2
__global__ void __launch_bounds__(256) emb_kernel(
    const float* __restrict__ coords,
    const float* __restrict__ W1,  const float* __restrict__ b1,
    const float* __restrict__ W2,  const float* __restrict__ b2,
    const float* __restrict__ Wd1, const float* __restrict__ bd1,
    const float* __restrict__ Wd2, const float* __restrict__ bd2,
    float* __restrict__ out)
{
    __shared__ u32   Asm[RB * ASTR];    //  9.2 KB  A[r][k] tf32
    __shared__ u32   Bsm[KC * BSTR];    // 33.8 KB  B[k][n] tf32
    __shared__ float2 xs[RB];
    __shared__ float  ms[RB];
    __shared__ float  bsum[HDIM];

    int tid  = threadIdx.x;
    int warp = tid >> 5;
    int lane = tid & 31;
    int g    = lane >> 2;      // 0..7
    int t    = lane & 3;       // 0..3
    int r0   = blockIdx.x * RB;
    int wr   = (warp & 3) * 16;        // warp row offset in block (0..48)
    int wn   = (warp >> 2) * 128;      // warp col offset (0 or 128)

    if (tid < RB) {
        xs[tid] = ((const float2*)coords)[r0 + tid];
        ms[tid] = g_mean[r0 + tid];
    }
    bsum[tid] = b2[tid] + bd2[tid];
    __syncthreads();

    float c[16][4];
    #pragma unroll
    for (int i = 0; i < 16; i++)
        #pragma unroll
        for (int j = 0; j < 4; j++) c[i][j] = 0.0f;

    for (int kc = 0; kc < KTOT; kc += KC) {
        // ---- A fill: silu activations for this k-chunk (8 values/thread)
        #pragma unroll
        for (int j = 0; j < 8; j++) {
            int i  = (j << 8) + tid;      // 0..2047
            int r  = i >> 5;
            int kk = i & 31;
            int k  = kc + kk;
            float h;
            if (k < HDIM) {
                float2 x = xs[r];
                h = fmaf(x.x, W1[k], fmaf(x.y, W1[HDIM + k], b1[k]));
            } else {
                h = fmaf(ms[r], Wd1[k - HDIM], bd1[k - HDIM]);
            }
            float sg = 1.0f / (1.0f + __expf(-h));
            Asm[r * ASTR + kk] = f2tf32(h * sg);
        }
        // ---- B fill: weights (32 values/thread, coalesced over n=tid)
        #pragma unroll 4
        for (int j = 0; j < KC; j++) {
            int k = kc + j;
            float wv = (k < HDIM) ? W2[k * HDIM + tid]
                                  : Wd2[(k - HDIM) * HDIM + tid];
            Bsm[j * BSTR + tid] = f2tf32(wv);
        }
        __syncthreads();

        // ---- MMA over this chunk
        #pragma unroll
        for (int ks = 0; ks < KC / 8; ks++) {
            int ak = ks * 8;
            u32 a0 = Asm[(wr + g)     * ASTR + ak + t];
            u32 a1 = Asm[(wr + g + 8) * ASTR + ak + t];
            u32 a2 = Asm[(wr + g)     * ASTR + ak + t + 4];
            u32 a3 = Asm[(wr + g + 8) * ASTR + ak + t + 4];
            #pragma unroll
            for (int nt = 0; nt < 16; nt++) {
                int n0 = wn + nt * 8;
                u32 b0 = Bsm[(ak + t)     * BSTR + n0 + g];
                u32 b1v = Bsm[(ak + t + 4) * BSTR + n0 + g];
                mma_tf32(c[nt], a0, a1, a2, a3, b0, b1v);
            }
        }
        __syncthreads();
    }

    // ---- epilogue: bias add + f32x2 stores
    int row0 = r0 + wr + g;
    #pragma unroll
    for (int nt = 0; nt < 16; nt++) {
        int col = wn + nt * 8 + 2 * t;
        float bb0 = bsum[col], bb1 = bsum[col + 1];
        float2 v0 = make_float2(c[nt][0] + bb0, c[nt][1] + bb1);
        float2 v1 = make_float2(c[nt][2] + bb0, c[nt][3] + bb1);
        *(float2*)&out[row0 * HDIM + col]       = v0;
        *(float2*)&out[(row0 + 8) * HDIM + col] = v1;
    }
}

// ---------------- launch ----------------------------------------------------
extern "C" void kernel_launch(void* const* d_in, const int* in_sizes, int n_in,
                              void* d_out, int out_size)
{
    const float* coords = (const float*)d_in[0];
    const float* W1  = (const float*)d_in[1];
    const float* b1  = (const float*)d_in[2];
    const float* W2  = (const float*)d_in[3];
    const float* b2  = (const float*)d_in[4];
    const float* Wd1 = (const float*)d_in[5];
    const float* bd1 = (const float*)d_in[6];
    const float* Wd2 = (const float*)d_in[7];
    const float* bd2 = (const float*)d_in[8];
    float* out = (float*)d_out;

    zero_kernel<<<(NCELLS + 255) / 256, 256>>>();
    cellid_kernel<<<(NPTS + 255) / 256, 256>>>(coords);
    scan_kernel<<<1, 1024>>>();
    scatter_kernel<<<(NPTS + 255) / 256, 256>>>(coords);
    search_kernel<<<NPTS / 8, 256>>>();
    emb_kernel<<<NPTS / RB, 256>>>(coords, W1, b1, W2, b2,
                                   Wd1, bd1, Wd2, bd2, out);
}